// round 16
// baseline (speedup 1.0000x reference)
#include <cuda_runtime.h>
#include <cuda_fp16.h>
#include <stdint.h>

// DAGNNConv: 10-hop normalized propagation + sigmoid-gated combination.
// N=100000, D=64, E=1300000 (incl self-loops), K=10.
// R16: occupancy push — __launch_bounds__(256,6) on the 9 plain hops
// (regs<=42 -> 6 blocks/SM); bucket entries pre-scaled by 8 (uint4-row
// index) to drop per-edge IMADs. Rest unchanged from R15.

#define NNODES 100000
#define DIM    64
#define KHOPS  10
#define BCAP   64
#define NROWS  (NNODES + 1)           // +1 phantom zero row

__device__ int     g_deg[NNODES];
__device__ float   g_norm[NNODES];
__device__ int     g_bkt[(size_t)NNODES * BCAP];        // src*8 per dst
__device__ __half2 g_F16[(size_t)NROWS * 32];           // t0 = norm .* feats
__device__ __half2 g_H[(size_t)(KHOPS - 1) * NROWS * 32]; // t_1..t_9

// ---------------------------------------------------------------------------
__global__ void k_zero() {
    int i = blockIdx.x * blockDim.x + threadIdx.x;
    if (i < NNODES) g_deg[i] = 0;
}

// Fused count + bucket scatter; stores src pre-scaled by 8.
__global__ void k_count_scatter(const int* __restrict__ src,
                                const int* __restrict__ dst, int nE) {
    int q = blockIdx.x * blockDim.x + threadIdx.x;
    int nq = nE >> 2;
    if (q < nq) {
        int4 d4 = ((const int4*)dst)[q];
        int4 s4 = ((const int4*)src)[q];
        if ((unsigned)d4.x < NNODES) {
            int r = atomicAdd(&g_deg[d4.x], 1);
            if (r < BCAP) g_bkt[(size_t)d4.x * BCAP + r] = s4.x * 8;
        }
        if ((unsigned)d4.y < NNODES) {
            int r = atomicAdd(&g_deg[d4.y], 1);
            if (r < BCAP) g_bkt[(size_t)d4.y * BCAP + r] = s4.y * 8;
        }
        if ((unsigned)d4.z < NNODES) {
            int r = atomicAdd(&g_deg[d4.z], 1);
            if (r < BCAP) g_bkt[(size_t)d4.z * BCAP + r] = s4.z * 8;
        }
        if ((unsigned)d4.w < NNODES) {
            int r = atomicAdd(&g_deg[d4.w], 1);
            if (r < BCAP) g_bkt[(size_t)d4.w * BCAP + r] = s4.w * 8;
        }
    } else if (q == nq) {
        for (int e = nq * 4; e < nE; e++) {
            unsigned d = (unsigned)dst[e];
            unsigned s = (unsigned)src[e];
            if (d < NNODES) {
                int r = atomicAdd(&g_deg[d], 1);
                if (r < BCAP) g_bkt[(size_t)d * BCAP + r] = (int)s * 8;
            }
        }
    }
}

__global__ void k_norm_cvt(const float* __restrict__ feats) {
    int i = blockIdx.x * blockDim.x + threadIdx.x;   // over NNODES*8
    if (i >= NNODES * 8) return;
    int v = i >> 3;
    float nv = rsqrtf((float)g_deg[v]);
    if ((i & 7) == 0) g_norm[v] = nv;
    float4 f0 = *(const float4*)(feats + (size_t)i * 8);
    float4 f1 = *(const float4*)(feats + (size_t)i * 8 + 4);
    uint4 o;
    *(__half2*)&o.x = __floats2half2_rn(f0.x * nv, f0.y * nv);
    *(__half2*)&o.y = __floats2half2_rn(f0.z * nv, f0.w * nv);
    *(__half2*)&o.z = __floats2half2_rn(f1.x * nv, f1.y * nv);
    *(__half2*)&o.w = __floats2half2_rn(f1.z * nv, f1.w * nv);
    ((uint4*)g_F16)[i] = o;
}

// ---------------------------------------------------------------------------
// Hop body macro (textual to avoid helper-function register bloat).
// Block owns 32 nodes, rank-sorted by degree; warp takes 4 rank-adjacent
// nodes; 8 lanes/node; lane owns 8 channels (16B gathers). Padded slots
// gather phantom zero row. Bucket entries pre-scaled: idx = rec + sub.

#define SPMM_PROLOGUE                                                        \
    __shared__ int sdeg[32], sperm[32];                                      \
    int tid = threadIdx.x;                                                   \
    int blockBase = blockIdx.x * 32;                                         \
    if (tid < 32) {                                                          \
        int v = blockBase + tid;                                             \
        if (v >= NNODES) v = NNODES - 1;                                     \
        int d = g_deg[v];                                                    \
        sdeg[tid] = (d < BCAP) ? d : BCAP;                                   \
    }                                                                        \
    __syncthreads();                                                         \
    if (tid < 32) {                                                          \
        int d = sdeg[tid];                                                   \
        int r = 0;                                                           \
        _Pragma("unroll")                                                    \
        for (int j = 0; j < 32; j++) {                                       \
            int dj = sdeg[j];                                                \
            r += (dj > d) || (dj == d && j < tid);                           \
        }                                                                    \
        sperm[r] = tid;                                                      \
    }                                                                        \
    __syncthreads();                                                         \
    int lane = tid & 31;                                                     \
    int sub  = lane & 7;                                                     \
    int gb   = lane & 24;                                                    \
    int slot = (tid >> 5) * 4 + (lane >> 3);                                 \
    int local = sperm[slot];                                                 \
    int v = blockBase + local;                                               \
    if (v >= NNODES) v = NNODES - 1;                                         \
    int deg = sdeg[local];                                                   \
    int maxdeg = sdeg[sperm[(tid >> 5) * 4]];                                \
    const int* __restrict__ row = g_bkt + (size_t)v * BCAP;                  \
    float nrm = g_norm[v];                                                   \
    float scale = nrm * nrm;                                                 \
    int nbatch = (maxdeg + 7) >> 3;                                          \
    float a0 = 0.f, a1 = 0.f, a2 = 0.f, a3 = 0.f;                            \
    float a4 = 0.f, a5 = 0.f, a6 = 0.f, a7 = 0.f;                            \
    int er = (sub < deg) ? row[sub] : NNODES * 8;                            \
    for (int b = 0; b < nbatch; b++) {                                       \
        int er_next = NNODES * 8;                                            \
        int nidx = (b + 1) * 8 + sub;                                        \
        if (b + 1 < nbatch && nidx < deg) er_next = row[nidx];               \
        int idxs[8];                                                         \
        _Pragma("unroll")                                                    \
        for (int j = 0; j < 8; j++)                                          \
            idxs[j] = __shfl_sync(0xFFFFFFFFu, er, gb + j) + sub;            \
        uint4 raws[8];                                                       \
        _Pragma("unroll")                                                    \
        for (int j = 0; j < 8; j++)                                          \
            raws[j] = prev[idxs[j]];                                         \
        uint4 m0, m1;                                                        \
        _Pragma("unroll")                                                    \
        for (int p = 0; p < 2; p++) {                                        \
            uint4* mp = p ? &m1 : &m0;                                       \
            __half2 hx = __hadd2(__hadd2(*(const __half2*)&raws[4*p].x,      \
                                         *(const __half2*)&raws[4*p+1].x),  \
                                 __hadd2(*(const __half2*)&raws[4*p+2].x,    \
                                         *(const __half2*)&raws[4*p+3].x)); \
            __half2 hy = __hadd2(__hadd2(*(const __half2*)&raws[4*p].y,      \
                                         *(const __half2*)&raws[4*p+1].y),  \
                                 __hadd2(*(const __half2*)&raws[4*p+2].y,    \
                                         *(const __half2*)&raws[4*p+3].y)); \
            __half2 hz = __hadd2(__hadd2(*(const __half2*)&raws[4*p].z,      \
                                         *(const __half2*)&raws[4*p+1].z),  \
                                 __hadd2(*(const __half2*)&raws[4*p+2].z,    \
                                         *(const __half2*)&raws[4*p+3].z)); \
            __half2 hw = __hadd2(__hadd2(*(const __half2*)&raws[4*p].w,      \
                                         *(const __half2*)&raws[4*p+1].w),  \
                                 __hadd2(*(const __half2*)&raws[4*p+2].w,    \
                                         *(const __half2*)&raws[4*p+3].w)); \
            *(__half2*)&mp->x = hx; *(__half2*)&mp->y = hy;                  \
            *(__half2*)&mp->z = hz; *(__half2*)&mp->w = hw;                  \
        }                                                                    \
        {                                                                    \
            float2 fx0 = __half22float2(*(const __half2*)&m0.x);             \
            float2 fy0 = __half22float2(*(const __half2*)&m0.y);             \
            float2 fz0 = __half22float2(*(const __half2*)&m0.z);             \
            float2 fw0 = __half22float2(*(const __half2*)&m0.w);             \
            float2 fx1 = __half22float2(*(const __half2*)&m1.x);             \
            float2 fy1 = __half22float2(*(const __half2*)&m1.y);             \
            float2 fz1 = __half22float2(*(const __half2*)&m1.z);             \
            float2 fw1 = __half22float2(*(const __half2*)&m1.w);             \
            a0 += fx0.x + fx1.x; a1 += fx0.y + fx1.y;                        \
            a2 += fy0.x + fy1.x; a3 += fy0.y + fy1.y;                        \
            a4 += fz0.x + fz1.x; a5 += fz0.y + fz1.y;                        \
            a6 += fw0.x + fw1.x; a7 += fw0.y + fw1.y;                        \
        }                                                                    \
        er = er_next;                                                        \
    }

// Hops 0..8: store t fp16. Occupancy-forced (6 blocks/SM).
__global__ void __launch_bounds__(256, 6)
k_spmm(int hop) {
    const uint4* __restrict__ prev = (const uint4*)(
        (hop == 0) ? g_F16 : (g_H + (size_t)(hop - 1) * NROWS * 32));
    uint4* __restrict__ cur = (uint4*)(g_H + (size_t)hop * NROWS * 32);
    SPMM_PROLOGUE
    uint4 o;
    *(__half2*)&o.x = __floats2half2_rn(a0 * scale, a1 * scale);
    *(__half2*)&o.y = __floats2half2_rn(a2 * scale, a3 * scale);
    *(__half2*)&o.z = __floats2half2_rn(a4 * scale, a5 * scale);
    *(__half2*)&o.w = __floats2half2_rn(a6 * scale, a7 * scale);
    cur[v * 8 + sub] = o;
}

// Hop 9 (the 10th) + fused gate: h10 = a * nrm from registers; slices
// k=0..9 from fp16 buffers (h_k = t_k / nrm).
__global__ void __launch_bounds__(256)
k_spmm_last(const float* __restrict__ s, float* __restrict__ out) {
    const uint4* __restrict__ prev =
        (const uint4*)(g_H + (size_t)(KHOPS - 2) * NROWS * 32);
    SPMM_PROLOGUE

    float rd = 1.0f / nrm;
    float4 s0 = *(const float4*)(s + sub * 8);
    float4 s1 = *(const float4*)(s + sub * 8 + 4);

    float c0 = 0.f, c1 = 0.f, c2 = 0.f, c3 = 0.f;
    float c4 = 0.f, c5 = 0.f, c6 = 0.f, c7 = 0.f;

#pragma unroll
    for (int k = 0; k <= KHOPS; k++) {
        float h0, h1, h2, h3, h4, h5, h6, h7;
        if (k < KHOPS) {
            const uint4* slice = (const uint4*)(
                (k == 0) ? g_F16 : (g_H + (size_t)(k - 1) * NROWS * 32));
            uint4 raw = slice[v * 8 + sub];
            float2 f0 = __half22float2(*(const __half2*)&raw.x);
            float2 f1 = __half22float2(*(const __half2*)&raw.y);
            float2 f2 = __half22float2(*(const __half2*)&raw.z);
            float2 f3 = __half22float2(*(const __half2*)&raw.w);
            h0 = f0.x * rd; h1 = f0.y * rd;
            h2 = f1.x * rd; h3 = f1.y * rd;
            h4 = f2.x * rd; h5 = f2.y * rd;
            h6 = f3.x * rd; h7 = f3.y * rd;
        } else {
            h0 = a0 * nrm; h1 = a1 * nrm; h2 = a2 * nrm; h3 = a3 * nrm;
            h4 = a4 * nrm; h5 = a5 * nrm; h6 = a6 * nrm; h7 = a7 * nrm;
        }
        float p = h0 * s0.x + h1 * s0.y + h2 * s0.z + h3 * s0.w +
                  h4 * s1.x + h5 * s1.y + h6 * s1.z + h7 * s1.w;
        p += __shfl_xor_sync(0xFFFFFFFFu, p, 1);
        p += __shfl_xor_sync(0xFFFFFFFFu, p, 2);
        p += __shfl_xor_sync(0xFFFFFFFFu, p, 4);
        float g = 1.f / (1.f + __expf(-p));
        c0 = fmaf(g, h0, c0); c1 = fmaf(g, h1, c1);
        c2 = fmaf(g, h2, c2); c3 = fmaf(g, h3, c3);
        c4 = fmaf(g, h4, c4); c5 = fmaf(g, h5, c5);
        c6 = fmaf(g, h6, c6); c7 = fmaf(g, h7, c7);
    }

    float4 o0, o1;
    o0.x = c0; o0.y = c1; o0.z = c2; o0.w = c3;
    o1.x = c4; o1.y = c5; o1.z = c6; o1.w = c7;
    *(float4*)(out + (size_t)v * DIM + sub * 8)     = o0;
    *(float4*)(out + (size_t)v * DIM + sub * 8 + 4) = o1;
}

// ---------------------------------------------------------------------------
extern "C" void kernel_launch(void* const* d_in, const int* in_sizes, int n_in,
                              void* d_out, int out_size) {
    const float* feats = (const float*)d_in[0];
    const float* s     = (const float*)d_in[1];
    const int*   src   = (const int*)d_in[2];
    const int*   dst   = (const int*)d_in[3];
    float*       out   = (float*)d_out;
    int nE = in_sizes[2];

    int qb = (nE / 4 + 256) / 256;
    int sb = (NNODES + 31) / 32;                   // 3125

    k_zero<<<(NNODES + 255) / 256, 256>>>();
    k_count_scatter<<<qb, 256>>>(src, dst, nE);
    k_norm_cvt<<<(NNODES * 8 + 255) / 256, 256>>>(feats);

    for (int hop = 0; hop < KHOPS - 1; hop++)
        k_spmm<<<sb, 256>>>(hop);

    k_spmm_last<<<sb, 256>>>(s, out);
}

// round 17
// speedup vs baseline: 1.1891x; 1.1891x over previous
#include <cuda_runtime.h>
#include <cuda_fp16.h>
#include <stdint.h>

// DAGNNConv: 10-hop normalized propagation + sigmoid-gated combination.
// N=100000, D=64, E=1300000 (incl self-loops), K=10.
// R17: revert R16's __launch_bounds__(256,6) (it spilled raws[8] -> local,
// 30.3us vs 22.7us). Keep pre-scaled bucket entries (src*8). Otherwise
// identical to R15 (best: 243.8us).

#define NNODES 100000
#define DIM    64
#define KHOPS  10
#define BCAP   64
#define NROWS  (NNODES + 1)           // +1 phantom zero row

__device__ int     g_deg[NNODES];
__device__ float   g_norm[NNODES];
__device__ int     g_bkt[(size_t)NNODES * BCAP];        // src*8 per dst
__device__ __half2 g_F16[(size_t)NROWS * 32];           // t0 = norm .* feats
__device__ __half2 g_H[(size_t)(KHOPS - 1) * NROWS * 32]; // t_1..t_9

// ---------------------------------------------------------------------------
__global__ void k_zero() {
    int i = blockIdx.x * blockDim.x + threadIdx.x;
    if (i < NNODES) g_deg[i] = 0;
}

// Fused count + bucket scatter; stores src pre-scaled by 8.
__global__ void k_count_scatter(const int* __restrict__ src,
                                const int* __restrict__ dst, int nE) {
    int q = blockIdx.x * blockDim.x + threadIdx.x;
    int nq = nE >> 2;
    if (q < nq) {
        int4 d4 = ((const int4*)dst)[q];
        int4 s4 = ((const int4*)src)[q];
        if ((unsigned)d4.x < NNODES) {
            int r = atomicAdd(&g_deg[d4.x], 1);
            if (r < BCAP) g_bkt[(size_t)d4.x * BCAP + r] = s4.x * 8;
        }
        if ((unsigned)d4.y < NNODES) {
            int r = atomicAdd(&g_deg[d4.y], 1);
            if (r < BCAP) g_bkt[(size_t)d4.y * BCAP + r] = s4.y * 8;
        }
        if ((unsigned)d4.z < NNODES) {
            int r = atomicAdd(&g_deg[d4.z], 1);
            if (r < BCAP) g_bkt[(size_t)d4.z * BCAP + r] = s4.z * 8;
        }
        if ((unsigned)d4.w < NNODES) {
            int r = atomicAdd(&g_deg[d4.w], 1);
            if (r < BCAP) g_bkt[(size_t)d4.w * BCAP + r] = s4.w * 8;
        }
    } else if (q == nq) {
        for (int e = nq * 4; e < nE; e++) {
            unsigned d = (unsigned)dst[e];
            unsigned s = (unsigned)src[e];
            if (d < NNODES) {
                int r = atomicAdd(&g_deg[d], 1);
                if (r < BCAP) g_bkt[(size_t)d * BCAP + r] = (int)s * 8;
            }
        }
    }
}

__global__ void k_norm_cvt(const float* __restrict__ feats) {
    int i = blockIdx.x * blockDim.x + threadIdx.x;   // over NNODES*8
    if (i >= NNODES * 8) return;
    int v = i >> 3;
    float nv = rsqrtf((float)g_deg[v]);
    if ((i & 7) == 0) g_norm[v] = nv;
    float4 f0 = *(const float4*)(feats + (size_t)i * 8);
    float4 f1 = *(const float4*)(feats + (size_t)i * 8 + 4);
    uint4 o;
    *(__half2*)&o.x = __floats2half2_rn(f0.x * nv, f0.y * nv);
    *(__half2*)&o.y = __floats2half2_rn(f0.z * nv, f0.w * nv);
    *(__half2*)&o.z = __floats2half2_rn(f1.x * nv, f1.y * nv);
    *(__half2*)&o.w = __floats2half2_rn(f1.z * nv, f1.w * nv);
    ((uint4*)g_F16)[i] = o;
}

// ---------------------------------------------------------------------------
// Hop body macro (textual to avoid helper-function register bloat).
// Block owns 32 nodes, rank-sorted by degree; warp takes 4 rank-adjacent
// nodes; 8 lanes/node; lane owns 8 channels (16B gathers). Padded slots
// gather phantom zero row. Bucket entries pre-scaled: idx = rec + sub.

#define SPMM_PROLOGUE                                                        \
    __shared__ int sdeg[32], sperm[32];                                      \
    int tid = threadIdx.x;                                                   \
    int blockBase = blockIdx.x * 32;                                         \
    if (tid < 32) {                                                          \
        int v = blockBase + tid;                                             \
        if (v >= NNODES) v = NNODES - 1;                                     \
        int d = g_deg[v];                                                    \
        sdeg[tid] = (d < BCAP) ? d : BCAP;                                   \
    }                                                                        \
    __syncthreads();                                                         \
    if (tid < 32) {                                                          \
        int d = sdeg[tid];                                                   \
        int r = 0;                                                           \
        _Pragma("unroll")                                                    \
        for (int j = 0; j < 32; j++) {                                       \
            int dj = sdeg[j];                                                \
            r += (dj > d) || (dj == d && j < tid);                           \
        }                                                                    \
        sperm[r] = tid;                                                      \
    }                                                                        \
    __syncthreads();                                                         \
    int lane = tid & 31;                                                     \
    int sub  = lane & 7;                                                     \
    int gb   = lane & 24;                                                    \
    int slot = (tid >> 5) * 4 + (lane >> 3);                                 \
    int local = sperm[slot];                                                 \
    int v = blockBase + local;                                               \
    if (v >= NNODES) v = NNODES - 1;                                         \
    int deg = sdeg[local];                                                   \
    int maxdeg = sdeg[sperm[(tid >> 5) * 4]];                                \
    const int* __restrict__ row = g_bkt + (size_t)v * BCAP;                  \
    float nrm = g_norm[v];                                                   \
    float scale = nrm * nrm;                                                 \
    int nbatch = (maxdeg + 7) >> 3;                                          \
    float a0 = 0.f, a1 = 0.f, a2 = 0.f, a3 = 0.f;                            \
    float a4 = 0.f, a5 = 0.f, a6 = 0.f, a7 = 0.f;                            \
    int er = (sub < deg) ? row[sub] : NNODES * 8;                            \
    for (int b = 0; b < nbatch; b++) {                                       \
        int er_next = NNODES * 8;                                            \
        int nidx = (b + 1) * 8 + sub;                                        \
        if (b + 1 < nbatch && nidx < deg) er_next = row[nidx];               \
        int idxs[8];                                                         \
        _Pragma("unroll")                                                    \
        for (int j = 0; j < 8; j++)                                          \
            idxs[j] = __shfl_sync(0xFFFFFFFFu, er, gb + j) + sub;            \
        uint4 raws[8];                                                       \
        _Pragma("unroll")                                                    \
        for (int j = 0; j < 8; j++)                                          \
            raws[j] = prev[idxs[j]];                                         \
        uint4 m0, m1;                                                        \
        _Pragma("unroll")                                                    \
        for (int p = 0; p < 2; p++) {                                        \
            uint4* mp = p ? &m1 : &m0;                                       \
            __half2 hx = __hadd2(__hadd2(*(const __half2*)&raws[4*p].x,      \
                                         *(const __half2*)&raws[4*p+1].x),  \
                                 __hadd2(*(const __half2*)&raws[4*p+2].x,    \
                                         *(const __half2*)&raws[4*p+3].x)); \
            __half2 hy = __hadd2(__hadd2(*(const __half2*)&raws[4*p].y,      \
                                         *(const __half2*)&raws[4*p+1].y),  \
                                 __hadd2(*(const __half2*)&raws[4*p+2].y,    \
                                         *(const __half2*)&raws[4*p+3].y)); \
            __half2 hz = __hadd2(__hadd2(*(const __half2*)&raws[4*p].z,      \
                                         *(const __half2*)&raws[4*p+1].z),  \
                                 __hadd2(*(const __half2*)&raws[4*p+2].z,    \
                                         *(const __half2*)&raws[4*p+3].z)); \
            __half2 hw = __hadd2(__hadd2(*(const __half2*)&raws[4*p].w,      \
                                         *(const __half2*)&raws[4*p+1].w),  \
                                 __hadd2(*(const __half2*)&raws[4*p+2].w,    \
                                         *(const __half2*)&raws[4*p+3].w)); \
            *(__half2*)&mp->x = hx; *(__half2*)&mp->y = hy;                  \
            *(__half2*)&mp->z = hz; *(__half2*)&mp->w = hw;                  \
        }                                                                    \
        {                                                                    \
            float2 fx0 = __half22float2(*(const __half2*)&m0.x);             \
            float2 fy0 = __half22float2(*(const __half2*)&m0.y);             \
            float2 fz0 = __half22float2(*(const __half2*)&m0.z);             \
            float2 fw0 = __half22float2(*(const __half2*)&m0.w);             \
            float2 fx1 = __half22float2(*(const __half2*)&m1.x);             \
            float2 fy1 = __half22float2(*(const __half2*)&m1.y);             \
            float2 fz1 = __half22float2(*(const __half2*)&m1.z);             \
            float2 fw1 = __half22float2(*(const __half2*)&m1.w);             \
            a0 += fx0.x + fx1.x; a1 += fx0.y + fx1.y;                        \
            a2 += fy0.x + fy1.x; a3 += fy0.y + fy1.y;                        \
            a4 += fz0.x + fz1.x; a5 += fz0.y + fz1.y;                        \
            a6 += fw0.x + fw1.x; a7 += fw0.y + fw1.y;                        \
        }                                                                    \
        er = er_next;                                                        \
    }

// Hops 0..8: store t fp16.
__global__ void __launch_bounds__(256)
k_spmm(int hop) {
    const uint4* __restrict__ prev = (const uint4*)(
        (hop == 0) ? g_F16 : (g_H + (size_t)(hop - 1) * NROWS * 32));
    uint4* __restrict__ cur = (uint4*)(g_H + (size_t)hop * NROWS * 32);
    SPMM_PROLOGUE
    uint4 o;
    *(__half2*)&o.x = __floats2half2_rn(a0 * scale, a1 * scale);
    *(__half2*)&o.y = __floats2half2_rn(a2 * scale, a3 * scale);
    *(__half2*)&o.z = __floats2half2_rn(a4 * scale, a5 * scale);
    *(__half2*)&o.w = __floats2half2_rn(a6 * scale, a7 * scale);
    cur[v * 8 + sub] = o;
}

// Hop 9 (the 10th) + fused gate: h10 = a * nrm from registers; slices
// k=0..9 from fp16 buffers (h_k = t_k / nrm).
__global__ void __launch_bounds__(256)
k_spmm_last(const float* __restrict__ s, float* __restrict__ out) {
    const uint4* __restrict__ prev =
        (const uint4*)(g_H + (size_t)(KHOPS - 2) * NROWS * 32);
    SPMM_PROLOGUE

    float rd = 1.0f / nrm;
    float4 s0 = *(const float4*)(s + sub * 8);
    float4 s1 = *(const float4*)(s + sub * 8 + 4);

    float c0 = 0.f, c1 = 0.f, c2 = 0.f, c3 = 0.f;
    float c4 = 0.f, c5 = 0.f, c6 = 0.f, c7 = 0.f;

#pragma unroll
    for (int k = 0; k <= KHOPS; k++) {
        float h0, h1, h2, h3, h4, h5, h6, h7;
        if (k < KHOPS) {
            const uint4* slice = (const uint4*)(
                (k == 0) ? g_F16 : (g_H + (size_t)(k - 1) * NROWS * 32));
            uint4 raw = slice[v * 8 + sub];
            float2 f0 = __half22float2(*(const __half2*)&raw.x);
            float2 f1 = __half22float2(*(const __half2*)&raw.y);
            float2 f2 = __half22float2(*(const __half2*)&raw.z);
            float2 f3 = __half22float2(*(const __half2*)&raw.w);
            h0 = f0.x * rd; h1 = f0.y * rd;
            h2 = f1.x * rd; h3 = f1.y * rd;
            h4 = f2.x * rd; h5 = f2.y * rd;
            h6 = f3.x * rd; h7 = f3.y * rd;
        } else {
            h0 = a0 * nrm; h1 = a1 * nrm; h2 = a2 * nrm; h3 = a3 * nrm;
            h4 = a4 * nrm; h5 = a5 * nrm; h6 = a6 * nrm; h7 = a7 * nrm;
        }
        float p = h0 * s0.x + h1 * s0.y + h2 * s0.z + h3 * s0.w +
                  h4 * s1.x + h5 * s1.y + h6 * s1.z + h7 * s1.w;
        p += __shfl_xor_sync(0xFFFFFFFFu, p, 1);
        p += __shfl_xor_sync(0xFFFFFFFFu, p, 2);
        p += __shfl_xor_sync(0xFFFFFFFFu, p, 4);
        float g = 1.f / (1.f + __expf(-p));
        c0 = fmaf(g, h0, c0); c1 = fmaf(g, h1, c1);
        c2 = fmaf(g, h2, c2); c3 = fmaf(g, h3, c3);
        c4 = fmaf(g, h4, c4); c5 = fmaf(g, h5, c5);
        c6 = fmaf(g, h6, c6); c7 = fmaf(g, h7, c7);
    }

    float4 o0, o1;
    o0.x = c0; o0.y = c1; o0.z = c2; o0.w = c3;
    o1.x = c4; o1.y = c5; o1.z = c6; o1.w = c7;
    *(float4*)(out + (size_t)v * DIM + sub * 8)     = o0;
    *(float4*)(out + (size_t)v * DIM + sub * 8 + 4) = o1;
}

// ---------------------------------------------------------------------------
extern "C" void kernel_launch(void* const* d_in, const int* in_sizes, int n_in,
                              void* d_out, int out_size) {
    const float* feats = (const float*)d_in[0];
    const float* s     = (const float*)d_in[1];
    const int*   src   = (const int*)d_in[2];
    const int*   dst   = (const int*)d_in[3];
    float*       out   = (float*)d_out;
    int nE = in_sizes[2];

    int qb = (nE / 4 + 256) / 256;
    int sb = (NNODES + 31) / 32;                   // 3125

    k_zero<<<(NNODES + 255) / 256, 256>>>();
    k_count_scatter<<<qb, 256>>>(src, dst, nE);
    k_norm_cvt<<<(NNODES * 8 + 255) / 256, 256>>>(feats);

    for (int hop = 0; hop < KHOPS - 1; hop++)
        k_spmm<<<sb, 256>>>(hop);

    k_spmm_last<<<sb, 256>>>(s, out);
}